// round 16
// baseline (speedup 1.0000x reference)
#include <cuda_runtime.h>
#include <cuda_bf16.h>
#include <math.h>
#include <stdint.h>

#define BATCH 2
#define NPTS 8192
#define NB (BATCH * NPTS)       // 16384
#define KNN 24
#define DM 128
#define PE_D 60
#define RROWS (NB * KNN)        // 393216

// ---------------- static device scratch ----------------
__device__ float  g_x[(size_t)NB * DM];          // x = features@fc1+b
__device__ float4 g_xyzw[NB];                    // xyz + 0.5*sqnorm
__device__ int    g_idx[(size_t)NB * KNN];
__device__ float  g_bufA[(size_t)RROWS * DM];    // h1 -> h2
__device__ float  g_bufB[(size_t)RROWS * DM];    // pos_enc
__device__ float  g_res0[(size_t)NB * DM];

// ---------------- f32x2 helpers ----------------
__device__ __forceinline__ unsigned long long pk2(float x, float y) {
    unsigned long long r;
    asm("mov.b64 %0, {%1, %2};" : "=l"(r) : "f"(x), "f"(y));
    return r;
}
__device__ __forceinline__ void fma2(unsigned long long& d, unsigned long long a,
                                     unsigned long long b) {
    asm("fma.rn.f32x2 %0, %1, %2, %0;" : "+l"(d) : "l"(a), "l"(b));
}
__device__ __forceinline__ void upk2(unsigned long long v, float& x, float& y) {
    asm("mov.b64 {%0, %1}, %2;" : "=f"(x), "=f"(y) : "l"(v));
}
__device__ __forceinline__ uint32_t smem_u32(const void* p) {
    uint32_t a;
    asm("{ .reg .u64 t; cvta.to.shared.u64 t, %1; cvt.u32.u64 %0, t; }" : "=r"(a) : "l"(p));
    return a;
}

// ---------------- kernel 1: x = features@fc1 + b, pack xyz + 0.5*sq ----------------
__global__ void k_fc1(const float* __restrict__ feat, const float* __restrict__ xyz,
                      const float* __restrict__ w, const float* __restrict__ b) {
    __shared__ float sf[8][32];
    int n0 = blockIdx.x * 8;
    int t = threadIdx.x;
    for (int e = t; e < 8 * 32; e += 128)
        sf[e / 32][e % 32] = feat[(size_t)(n0 + e / 32) * 32 + (e % 32)];
    __syncthreads();
    float acc[8];
#pragma unroll
    for (int r = 0; r < 8; ++r) acc[r] = 0.0f;
    int d = t;
    for (int c = 0; c < 32; ++c) {
        float wv = w[c * DM + d];
#pragma unroll
        for (int r = 0; r < 8; ++r) acc[r] = fmaf(sf[r][c], wv, acc[r]);
    }
    float bv = b[d];
#pragma unroll
    for (int r = 0; r < 8; ++r)
        g_x[(size_t)(n0 + r) * DM + d] = acc[r] + bv;
    if (t < 8) {
        int n = n0 + t;
        float x0 = xyz[(size_t)n * 3 + 0];
        float x1 = xyz[(size_t)n * 3 + 1];
        float x2 = xyz[(size_t)n * 3 + 2];
        float sq = __fadd_rn(__fadd_rn(__fmul_rn(x0, x0), __fmul_rn(x1, x1)), __fmul_rn(x2, x2));
        g_xyzw[n] = make_float4(x0, x1, x2, 0.5f * sq);
    }
}

// ---------------- kernel 2: KNN — 2 threads/query, register top-K (R15 locked) ----------------
#define KNN_SMEM (16384 + 24576 + 24576)
__global__ void __launch_bounds__(256) k_knn() {
    extern __shared__ char sm[];
    float4* tile = reinterpret_cast<float4*>(sm);              // [1024]
    float*  skey = reinterpret_cast<float*>(sm + 16384);       // [128][48]
    int*    sidx = reinterpret_cast<int*>(sm + 16384 + 24576); // [128][48]

    int tid = threadIdx.x;
    int ql = tid & 127;
    int p = tid >> 7;
    int q = blockIdx.x * 128 + ql;
    int base = (q >> 13) << 13;

    float4 qv = g_xyzw[q];
    float qnx = -qv.x, qny = -qv.y, qnz = -qv.z;

    float kd[KNN];
    int   ki[KNN];
#pragma unroll
    for (int i = 0; i < KNN; ++i) { kd[i] = INFINITY; ki[i] = 0x7fffffff; }
    float wk = INFINITY;

    for (int t0 = 0; t0 < NPTS; t0 += 1024) {
        __syncthreads();
        for (int i = tid; i < 1024; i += 256)
            tile[i] = g_xyzw[base + t0 + i];
        __syncthreads();
        const float4* tp = tile + p * 512;
        int ib = t0 + p * 512;
        for (int i = 0; i < 512; ++i) {
            float4 c = tp[i];
            float key = __fmaf_rn(qnx, c.x, __fmaf_rn(qny, c.y, __fmaf_rn(qnz, c.z, c.w)));
            if (key < wk) {
                int bestki = -1, sel = 0;
#pragma unroll
                for (int k = 0; k < KNN; ++k) {
                    bool m = (kd[k] == wk) && (ki[k] > bestki);
                    if (m) { bestki = ki[k]; sel = k; }
                }
#pragma unroll
                for (int k = 0; k < KNN; ++k) {
                    if (k == sel) { kd[k] = key; ki[k] = ib + i; }
                }
                float m0 = kd[0];
#pragma unroll
                for (int k = 1; k < KNN; ++k) m0 = fmaxf(m0, kd[k]);
                wk = m0;
            }
        }
    }

    float* myk = skey + ql * 48 + p * 24;
    int*   myi = sidx + ql * 48 + p * 24;
#pragma unroll 1
    for (int k = 0; k < KNN; ++k) {
        float bk = kd[0]; int bi = ki[0]; int bs = 0;
#pragma unroll
        for (int j = 1; j < KNN; ++j) {
            bool lt = (kd[j] < bk) || (kd[j] == bk && ki[j] < bi);
            if (lt) { bk = kd[j]; bi = ki[j]; bs = j; }
        }
        myk[k] = bk; myi[k] = bi;
#pragma unroll
        for (int j = 0; j < KNN; ++j) {
            if (j == bs) { kd[j] = INFINITY; ki[j] = 0x7fffffff; }
        }
    }
    __syncthreads();

    if (p == 0) {
        const float* k0 = skey + ql * 48;
        const int*   i0 = sidx + ql * 48;
        const float* k1 = k0 + 24;
        const int*   i1 = i0 + 24;
        int a = 0, b = 0;
#pragma unroll
        for (int k = 0; k < KNN; ++k) {
            float ka = k0[a], kb = k1[b];
            int ia = i0[a], ic = i1[b];
            bool takeA = (ka < kb) || (ka == kb && ia < ic);
            g_idx[(size_t)q * KNN + k] = takeA ? ia : ic;
            if (takeA) ++a; else ++b;
        }
    }
}

// ---------------- kernel 3: pe + h1, 2 nodes per 256-thread block ----------------
__global__ void __launch_bounds__(256) k_pe(const float* __restrict__ d1w,
                                            const float* __restrict__ d1b) {
    int n0 = blockIdx.x * 2;
    int t = threadIdx.x;
    int nl = t >> 7;
    int d = t & 127;
    int nn = n0 + nl;

    __shared__ float w1[PE_D * DM];
    __shared__ float pe_t[2][PE_D * KNN];
    __shared__ float gk[2][KNN][3];

    for (int e = t; e < PE_D * DM; e += 256) w1[e] = d1w[e];
    if (t < 2 * KNN * 3) {
        int nodeL = t / (KNN * 3);
        int rem = t % (KNN * 3);
        int k = rem / 3, c = rem % 3;
        int node = n0 + nodeL;
        int bb = (node >> 13) << 13;
        int id = g_idx[(size_t)node * KNN + k];
        float4 q = g_xyzw[node];
        float4 cc = g_xyzw[bb + id];
        float qc = (c == 0) ? q.x : (c == 1) ? q.y : q.z;
        float kc = (c == 0) ? cc.x : (c == 1) ? cc.y : cc.z;
        gk[nodeL][k][c] = qc - kc;
    }
    __syncthreads();

    const float LOGC = -1.3287712379549449f;
    for (int e = t; e < 2 * KNN * PE_D; e += 256) {
        int nodeL = e / (KNN * PE_D);
        int rem = e % (KNN * PE_D);
        int k = rem / PE_D, j = rem % PE_D;
        int c = j / 20, r = j % 20, m = r % 10;
        float om = exp2f((float)m * LOGC);
        float ph = gk[nodeL][k][c] * om;
        pe_t[nodeL][j * KNN + k] = (r < 10) ? __sinf(ph) : __cosf(ph);
    }
    __syncthreads();

    unsigned long long acc2[12];
#pragma unroll
    for (int m = 0; m < 12; ++m) acc2[m] = 0ull;
    for (int j = 0; j < PE_D; ++j) {
        float wv = w1[j * DM + d];
        unsigned long long w2 = pk2(wv, wv);
        const unsigned long long* pr =
            reinterpret_cast<const unsigned long long*>(&pe_t[nl][j * KNN]);
#pragma unroll
        for (int m = 0; m < 12; ++m) fma2(acc2[m], pr[m], w2);
    }
    float bv = d1b[d];
#pragma unroll
    for (int m = 0; m < 12; ++m) {
        float a0, a1;
        upk2(acc2[m], a0, a1);
        g_bufA[((size_t)nn * KNN + 2 * m) * DM + d] = fmaxf(a0 + bv, 0.0f);
        g_bufA[((size_t)nn * KNN + 2 * m + 1) * DM + d] = fmaxf(a1 + bv, 0.0f);
    }
}

// ---------------- fused GEMM d2+g1: BM=64, attn_in resident in smem ----------------
// pass 1: pos_enc = h1@d2+b -> bufB ; attn_in -> smem Ares
// pass 2: h2 = relu(attn_in@g1+b) -> bufA
#define F_ASTREAM (2 * 64 * 36)              // 4608 floats
#define F_W (2 * 32 * 128)                   // 8192 floats
#define F_ARES (64 * 132)                    // 8448 floats
#define SMEM01 ((F_ASTREAM + F_W + F_ARES) * 4)   // 84992 B

__global__ void __launch_bounds__(256, 2)
k_gemm01(const float* __restrict__ A, const float* __restrict__ Wd2,
         const float* __restrict__ Wg1, const float* __restrict__ bd2,
         const float* __restrict__ bg1, float* __restrict__ outH2) {
    extern __shared__ float smf[];
    float* Asm = smf;                        // [2][64][36]
    float* Wsm = smf + F_ASTREAM;            // [2][32][128]
    float* Ares = smf + F_ASTREAM + F_W;     // [64][132]
    uint32_t sA = smem_u32(Asm);
    uint32_t sW = smem_u32(Wsm);

    int r0 = blockIdx.x * 64;
    int tid = threadIdx.x;
    int tx = tid & 15, ty = tid >> 4;

    unsigned long long acc2[4][4];
#pragma unroll
    for (int i = 0; i < 4; ++i)
#pragma unroll
        for (int j = 0; j < 4; ++j) acc2[i][j] = 0ull;

    // ---- pass 1 prologue: A(h1) + W(d2) tile 0 ----
    {
#pragma unroll
        for (int u = 0; u < 2; ++u) {
            int e = tid + u * 256;
            int row = e >> 3, c = e & 7;
            uint32_t sa = sA + (uint32_t)(row * 36 + c * 4) * 4;
            const float* ga = A + (size_t)(r0 + row) * 128 + c * 4;
            asm volatile("cp.async.cg.shared.global [%0], [%1], 16;" :: "r"(sa), "l"(ga));
        }
#pragma unroll
        for (int u = 0; u < 4; ++u) {
            int e = tid + u * 256;
            int kr = e >> 5, c = e & 31;
            uint32_t sw = sW + (uint32_t)(kr * 128 + c * 4) * 4;
            const float* gw = Wd2 + (size_t)kr * 128 + c * 4;
            asm volatile("cp.async.cg.shared.global [%0], [%1], 16;" :: "r"(sw), "l"(gw));
        }
        asm volatile("cp.async.commit_group;");
    }

    // ---- pass 1 K-loop ----
#pragma unroll 1
    for (int kt = 0; kt < 128; kt += 32) {
        int buf = (kt >> 5) & 1;
        if (kt < 96) {
            int nb = buf ^ 1;
#pragma unroll
            for (int u = 0; u < 2; ++u) {
                int e = tid + u * 256;
                int row = e >> 3, c = e & 7;
                uint32_t sa = sA + (uint32_t)(nb * (64 * 36) + row * 36 + c * 4) * 4;
                const float* ga = A + (size_t)(r0 + row) * 128 + (kt + 32) + c * 4;
                asm volatile("cp.async.cg.shared.global [%0], [%1], 16;" :: "r"(sa), "l"(ga));
            }
#pragma unroll
            for (int u = 0; u < 4; ++u) {
                int e = tid + u * 256;
                int kr = e >> 5, c = e & 31;
                uint32_t sw = sW + (uint32_t)(nb * 4096 + kr * 128 + c * 4) * 4;
                const float* gw = Wd2 + (size_t)(kt + 32 + kr) * 128 + c * 4;
                asm volatile("cp.async.cg.shared.global [%0], [%1], 16;" :: "r"(sw), "l"(gw));
            }
            asm volatile("cp.async.commit_group;");
            asm volatile("cp.async.wait_group 1;");
        } else {
            asm volatile("cp.async.wait_group 0;");
        }
        __syncthreads();

        const float* Ab = Asm + buf * (64 * 36) + (ty * 4) * 36;
        const float* Wb = Wsm + buf * 4096;
#pragma unroll
        for (int kk = 0; kk < 32; ++kk) {
            ulonglong2 wq0 = *reinterpret_cast<const ulonglong2*>(Wb + kk * 128 + tx * 8);
            ulonglong2 wq1 = *reinterpret_cast<const ulonglong2*>(Wb + kk * 128 + tx * 8 + 4);
            unsigned long long w2[4] = {wq0.x, wq0.y, wq1.x, wq1.y};
#pragma unroll
            for (int i = 0; i < 4; ++i) {
                float av = Ab[i * 36 + kk];
                unsigned long long a2 = pk2(av, av);
#pragma unroll
                for (int j = 0; j < 4; ++j) fma2(acc2[i][j], a2, w2[j]);
            }
        }
        __syncthreads();
    }

    // ---- pass 1 epilogue: pos_enc -> bufB, attn_in -> Ares ----
    int col = tx * 8;
    {
        float4 b0 = *reinterpret_cast<const float4*>(bd2 + col);
        float4 b1 = *reinterpret_cast<const float4*>(bd2 + col + 4);
        float bc[8] = {b0.x, b0.y, b0.z, b0.w, b1.x, b1.y, b1.z, b1.w};
#pragma unroll
        for (int i = 0; i < 4; ++i) {
            int R = r0 + ty * 4 + i;
            float o[8];
#pragma unroll
            for (int j = 0; j < 4; ++j) upk2(acc2[i][j], o[2 * j], o[2 * j + 1]);
#pragma unroll
            for (int j = 0; j < 8; ++j) o[j] += bc[j];
            int n = R / KNN;
            int kid = g_idx[R];
            int base = (n >> 13) << 13;
            const float* xn = g_x + (size_t)n * 128 + col;
            const float* xk = g_x + (size_t)(base + kid) * 128 + col;
            float4 n0 = *reinterpret_cast<const float4*>(xn);
            float4 n1 = *reinterpret_cast<const float4*>(xn + 4);
            float4 k0 = *reinterpret_cast<const float4*>(xk);
            float4 k1 = *reinterpret_cast<const float4*>(xk + 4);
            size_t off = (size_t)R * 128 + col;
            *reinterpret_cast<float4*>(g_bufB + off) = make_float4(o[0], o[1], o[2], o[3]);
            *reinterpret_cast<float4*>(g_bufB + off + 4) = make_float4(o[4], o[5], o[6], o[7]);
            float4 A0 = make_float4((n0.x - k0.x) + o[0], (n0.y - k0.y) + o[1],
                                    (n0.z - k0.z) + o[2], (n0.w - k0.w) + o[3]);
            float4 A1 = make_float4((n1.x - k1.x) + o[4], (n1.y - k1.y) + o[5],
                                    (n1.z - k1.z) + o[6], (n1.w - k1.w) + o[7]);
            float* ar = Ares + (ty * 4 + i) * 132 + col;
            *reinterpret_cast<float4*>(ar) = A0;
            *reinterpret_cast<float4*>(ar + 4) = A1;
        }
    }
    __syncthreads();   // Ares visible; pass-1 W reads done

    // ---- pass 2 prologue: W(g1) tile 0 ----
#pragma unroll
    for (int i = 0; i < 4; ++i)
#pragma unroll
        for (int j = 0; j < 4; ++j) acc2[i][j] = 0ull;
    {
#pragma unroll
        for (int u = 0; u < 4; ++u) {
            int e = tid + u * 256;
            int kr = e >> 5, c = e & 31;
            uint32_t sw = sW + (uint32_t)(kr * 128 + c * 4) * 4;
            const float* gw = Wg1 + (size_t)kr * 128 + c * 4;
            asm volatile("cp.async.cg.shared.global [%0], [%1], 16;" :: "r"(sw), "l"(gw));
        }
        asm volatile("cp.async.commit_group;");
    }

    // ---- pass 2 K-loop (A from resident Ares) ----
#pragma unroll 1
    for (int kt = 0; kt < 128; kt += 32) {
        int buf = (kt >> 5) & 1;
        if (kt < 96) {
            int nb = buf ^ 1;
#pragma unroll
            for (int u = 0; u < 4; ++u) {
                int e = tid + u * 256;
                int kr = e >> 5, c = e & 31;
                uint32_t sw = sW + (uint32_t)(nb * 4096 + kr * 128 + c * 4) * 4;
                const float* gw = Wg1 + (size_t)(kt + 32 + kr) * 128 + c * 4;
                asm volatile("cp.async.cg.shared.global [%0], [%1], 16;" :: "r"(sw), "l"(gw));
            }
            asm volatile("cp.async.commit_group;");
            asm volatile("cp.async.wait_group 1;");
        } else {
            asm volatile("cp.async.wait_group 0;");
        }
        __syncthreads();

        const float* Ab = Ares + (ty * 4) * 132 + kt;
        const float* Wb = Wsm + buf * 4096;
#pragma unroll
        for (int kk = 0; kk < 32; ++kk) {
            ulonglong2 wq0 = *reinterpret_cast<const ulonglong2*>(Wb + kk * 128 + tx * 8);
            ulonglong2 wq1 = *reinterpret_cast<const ulonglong2*>(Wb + kk * 128 + tx * 8 + 4);
            unsigned long long w2[4] = {wq0.x, wq0.y, wq1.x, wq1.y};
#pragma unroll
            for (int i = 0; i < 4; ++i) {
                float av = Ab[i * 132 + kk];
                unsigned long long a2 = pk2(av, av);
#pragma unroll
                for (int j = 0; j < 4; ++j) fma2(acc2[i][j], a2, w2[j]);
            }
        }
        __syncthreads();
    }

    // ---- pass 2 epilogue: h2 = relu(. + bg1) -> outH2 ----
    {
        float4 b0 = *reinterpret_cast<const float4*>(bg1 + col);
        float4 b1 = *reinterpret_cast<const float4*>(bg1 + col + 4);
        float bc[8] = {b0.x, b0.y, b0.z, b0.w, b1.x, b1.y, b1.z, b1.w};
#pragma unroll
        for (int i = 0; i < 4; ++i) {
            int R = r0 + ty * 4 + i;
            float o[8];
#pragma unroll
            for (int j = 0; j < 4; ++j) upk2(acc2[i][j], o[2 * j], o[2 * j + 1]);
#pragma unroll
            for (int j = 0; j < 8; ++j) o[j] = fmaxf(o[j] + bc[j], 0.0f);
            size_t off = (size_t)R * 128 + col;
            *reinterpret_cast<float4*>(outH2 + off) = make_float4(o[0], o[1], o[2], o[3]);
            *reinterpret_cast<float4*>(outH2 + off + 4) = make_float4(o[4], o[5], o[6], o[7]);
        }
    }
}

// ---------------- g2 GEMM + fused softmax (R11/R15 proven, BM=96) ----------------
#define AS_STRIDE 36
#define WS_BUF (32 * 128)

template <int MODE, int BM>
__global__ void __launch_bounds__(256, 2)
k_gemm2(const float* __restrict__ A, const float* __restrict__ W,
        const float* __restrict__ bias, float* __restrict__ C) {
    constexpr int AS_BUF = BM * AS_STRIDE;
    constexpr int RPT = BM / 16;
    extern __shared__ float smf[];
    float* Asm = smf;
    float* Wsm = smf + 2 * AS_BUF;
    uint32_t sA = smem_u32(Asm);
    uint32_t sW = smem_u32(Wsm);

    int r0 = blockIdx.x * BM;
    int tid = threadIdx.x;
    int tx = tid & 15, ty = tid >> 4;

    unsigned long long acc2[RPT][4];
#pragma unroll
    for (int i = 0; i < RPT; ++i)
#pragma unroll
        for (int j = 0; j < 4; ++j) acc2[i][j] = 0ull;

    {
#pragma unroll
        for (int u = 0; u < BM / 32; ++u) {
            int e = tid + u * 256;
            int row = e >> 3, c = e & 7;
            uint32_t sa = sA + (uint32_t)(row * AS_STRIDE + c * 4) * 4;
            const float* ga = A + (size_t)(r0 + row) * 128 + c * 4;
            asm volatile("cp.async.cg.shared.global [%0], [%1], 16;" :: "r"(sa), "l"(ga));
        }
#pragma unroll
        for (int u = 0; u < 4; ++u) {
            int e = tid + u * 256;
            int kr = e >> 5, c = e & 31;
            uint32_t sw = sW + (uint32_t)(kr * 128 + c * 4) * 4;
            const float* gw = W + (size_t)kr * 128 + c * 4;
            asm volatile("cp.async.cg.shared.global [%0], [%1], 16;" :: "r"(sw), "l"(gw));
        }
        asm volatile("cp.async.commit_group;");
    }

#pragma unroll 1
    for (int kt = 0; kt < 128; kt += 32) {
        int buf = (kt >> 5) & 1;
        if (kt < 96) {
            int nb = buf ^ 1;
#pragma unroll
            for (int u = 0; u < BM / 32; ++u) {
                int e = tid + u * 256;
                int row = e >> 3, c = e & 7;
                uint32_t sa = sA + (uint32_t)(nb * AS_BUF + row * AS_STRIDE + c * 4) * 4;
                const float* ga = A + (size_t)(r0 + row) * 128 + (kt + 32) + c * 4;
                asm volatile("cp.async.cg.shared.global [%0], [%1], 16;" :: "r"(sa), "l"(ga));
            }
#pragma unroll
            for (int u = 0; u < 4; ++u) {
                int e = tid + u * 256;
                int kr = e >> 5, c = e & 31;
                uint32_t sw = sW + (uint32_t)(nb * WS_BUF + kr * 128 + c * 4) * 4;
                const float* gw = W + (size_t)(kt + 32 + kr) * 128 + c * 4;
                asm volatile("cp.async.cg.shared.global [%0], [%1], 16;" :: "r"(sw), "l"(gw));
            }
            asm volatile("cp.async.commit_group;");
            asm volatile("cp.async.wait_group 1;");
        } else {
            asm volatile("cp.async.wait_group 0;");
        }
        __syncthreads();

        const float* Ab = Asm + buf * AS_BUF + (ty * RPT) * AS_STRIDE;
        const float* Wb = Wsm + buf * WS_BUF;
#pragma unroll
        for (int kk = 0; kk < 32; ++kk) {
            ulonglong2 wq0 = *reinterpret_cast<const ulonglong2*>(Wb + kk * 128 + tx * 8);
            ulonglong2 wq1 = *reinterpret_cast<const ulonglong2*>(Wb + kk * 128 + tx * 8 + 4);
            unsigned long long w2[4] = {wq0.x, wq0.y, wq1.x, wq1.y};
#pragma unroll
            for (int i = 0; i < RPT; ++i) {
                float av = Ab[i * AS_STRIDE + kk];
                unsigned long long a2 = pk2(av, av);
#pragma unroll
                for (int j = 0; j < 4; ++j) fma2(acc2[i][j], a2, w2[j]);
            }
        }
        __syncthreads();
    }

    int col = tx * 8;

    if (MODE == 2) {
        float* stage = smf;
#pragma unroll
        for (int i = 0; i < RPT; ++i) {
            int row = ty * RPT + i;
            float o[8];
#pragma unroll
            for (int j = 0; j < 4; ++j) upk2(acc2[i][j], o[2 * j], o[2 * j + 1]);
#pragma unroll
            for (int j = 0; j < 4; ++j)
                *reinterpret_cast<float2*>(stage + row * 132 + col + 2 * j) =
                    make_float2(o[2 * j], o[2 * j + 1]);
        }
        __syncthreads();

        const float inv = 0.088388347648318447f;
#pragma unroll 1
        for (int jb = 0; jb < 2; ++jb) {
            int job = tid + jb * 256;
            int nl = job >> 7;
            int cc = job & 127;
            int node = blockIdx.x * 4 + nl;
            int base = (node >> 13) << 13;
            float bc = bias[cc];

            float a[KNN];
#pragma unroll
            for (int k = 0; k < KNN; ++k)
                a[k] = (stage[(nl * KNN + k) * 132 + cc] + bc) * inv;
            float m = a[0];
#pragma unroll
            for (int k = 1; k < KNN; ++k) m = fmaxf(m, a[k]);
            float s = 0.0f;
#pragma unroll
            for (int k = 0; k < KNN; ++k) { a[k] = expf(a[k] - m); s += a[k]; }
            float rs = 1.0f / s;

            float acc = 0.0f;
            size_t roff = (size_t)node * KNN * DM + cc;
#pragma unroll
            for (int k = 0; k < KNN; ++k) {
                float at = a[k] * rs;
                size_t po = roff + (size_t)k * DM;
                C[po] = at;
                int id = g_idx[(size_t)node * KNN + k];
                float vv = g_x[(size_t)(base + id) * DM + cc] + g_bufB[po];
                acc = fmaf(at, vv, acc);
            }
            g_res0[(size_t)node * DM + cc] = acc;
        }
        return;
    }
}

// ---------------- final: out = res0@fc2 + b + x ----------------
__global__ void k_final(const float* __restrict__ w, const float* __restrict__ b,
                        float* __restrict__ out_res) {
    __shared__ float s[8][DM];
    int n0 = blockIdx.x * 8;
    int t = threadIdx.x;
    for (int e = t; e < 8 * DM; e += 128)
        s[e >> 7][e & 127] = g_res0[(size_t)(n0 + (e >> 7)) * DM + (e & 127)];
    __syncthreads();
    float acc[8];
#pragma unroll
    for (int r = 0; r < 8; ++r) acc[r] = 0.0f;
    for (int c = 0; c < DM; ++c) {
        float wv = w[c * DM + t];
#pragma unroll
        for (int r = 0; r < 8; ++r) acc[r] = fmaf(s[r][c], wv, acc[r]);
    }
    float bv = b[t];
#pragma unroll
    for (int r = 0; r < 8; ++r)
        out_res[(size_t)(n0 + r) * DM + t] = (acc[r] + bv) + g_x[(size_t)(n0 + r) * DM + t];
}

// ---------------- launch ----------------
extern "C" void kernel_launch(void* const* d_in, const int* in_sizes, int n_in,
                              void* d_out, int out_size) {
    const float* features = (const float*)d_in[0];
    const float* xyz      = (const float*)d_in[1];
    const float* fc1_w    = (const float*)d_in[2];
    const float* fc1_b    = (const float*)d_in[3];
    const float* fc2_w    = (const float*)d_in[4];
    const float* fc2_b    = (const float*)d_in[5];
    const float* d1_w     = (const float*)d_in[6];
    const float* d1_b     = (const float*)d_in[7];
    const float* d2_w     = (const float*)d_in[8];
    const float* d2_b     = (const float*)d_in[9];
    const float* g1_w     = (const float*)d_in[10];
    const float* g1_b     = (const float*)d_in[11];
    const float* g2_w     = (const float*)d_in[12];
    const float* g2_b     = (const float*)d_in[13];

    float* out      = (float*)d_out;
    float* out_res  = out;
    float* out_attn = out + (size_t)NB * DM;

    float *pA = nullptr;
    cudaGetSymbolAddress((void**)&pA, g_bufA);

    const int SM96a = (2 * 96 * AS_STRIDE + 2 * WS_BUF) * 4;
    const int SM96b = 96 * 132 * 4;
    const int SM96 = SM96a > SM96b ? SM96a : SM96b;
    cudaFuncSetAttribute((const void*)k_knn, cudaFuncAttributeMaxDynamicSharedMemorySize, KNN_SMEM);
    cudaFuncSetAttribute((const void*)k_gemm01, cudaFuncAttributeMaxDynamicSharedMemorySize, SMEM01);
    cudaFuncSetAttribute((const void*)k_gemm2<2, 96>, cudaFuncAttributeMaxDynamicSharedMemorySize, SM96);

    // 1. x = features@fc1 + b ; xyzw pack (w = 0.5*||p||^2)
    k_fc1<<<NB / 8, 128>>>(features, xyz, fc1_w, fc1_b);
    // 2. KNN
    k_knn<<<NB / 128, 256, KNN_SMEM>>>();
    // 3. h1 = relu(pe@d1 + b) -> bufA
    k_pe<<<NB / 2, 256>>>(d1_w, d1_b);
    // 4+5. fused: pos_enc -> bufB ; h2 = relu(attn_in@g1+b) -> bufA
    k_gemm01<<<RROWS / 64, 256, SMEM01>>>(pA, d2_w, g1_w, d2_b, g1_b, pA);
    // 6. attn = softmax(h2@g2 + b) -> out_attn ; res0 (fused)
    k_gemm2<2, 96><<<RROWS / 96, 256, SM96>>>(pA, g2_w, g2_b, out_attn);
    // 7. res = res0@fc2 + b + x
    k_final<<<NB / 8, 128>>>(fc2_w, fc2_b, out_res);
}

// round 17
// speedup vs baseline: 1.1210x; 1.1210x over previous
#include <cuda_runtime.h>
#include <cuda_bf16.h>
#include <math.h>
#include <stdint.h>

#define BATCH 2
#define NPTS 8192
#define NB (BATCH * NPTS)       // 16384
#define KNN 24
#define DM 128
#define PE_D 60
#define RROWS (NB * KNN)        // 393216

// ---------------- static device scratch ----------------
__device__ float  g_x[(size_t)NB * DM];          // x = features@fc1+b
__device__ float4 g_xyzw[NB];                    // xyz + 0.5*sqnorm
__device__ int    g_idx[(size_t)NB * KNN];
__device__ float  g_bufA[(size_t)RROWS * DM];    // h1 -> attn_in -> h2
__device__ float  g_bufB[(size_t)RROWS * DM];    // pos_enc
__device__ float  g_res0[(size_t)NB * DM];

// ---------------- f32x2 helpers ----------------
__device__ __forceinline__ unsigned long long pk2(float x, float y) {
    unsigned long long r;
    asm("mov.b64 %0, {%1, %2};" : "=l"(r) : "f"(x), "f"(y));
    return r;
}
__device__ __forceinline__ void fma2(unsigned long long& d, unsigned long long a,
                                     unsigned long long b) {
    asm("fma.rn.f32x2 %0, %1, %2, %0;" : "+l"(d) : "l"(a), "l"(b));
}
__device__ __forceinline__ void upk2(unsigned long long v, float& x, float& y) {
    asm("mov.b64 {%0, %1}, %2;" : "=f"(x), "=f"(y) : "l"(v));
}
__device__ __forceinline__ uint32_t smem_u32(const void* p) {
    uint32_t a;
    asm("{ .reg .u64 t; cvta.to.shared.u64 t, %1; cvt.u32.u64 %0, t; }" : "=r"(a) : "l"(p));
    return a;
}

// ---------------- kernel 1: x = features@fc1 + b, pack xyz + 0.5*sq ----------------
__global__ void k_fc1(const float* __restrict__ feat, const float* __restrict__ xyz,
                      const float* __restrict__ w, const float* __restrict__ b) {
    __shared__ float sf[8][32];
    int n0 = blockIdx.x * 8;
    int t = threadIdx.x;
    for (int e = t; e < 8 * 32; e += 128)
        sf[e / 32][e % 32] = feat[(size_t)(n0 + e / 32) * 32 + (e % 32)];
    __syncthreads();
    float acc[8];
#pragma unroll
    for (int r = 0; r < 8; ++r) acc[r] = 0.0f;
    int d = t;
    for (int c = 0; c < 32; ++c) {
        float wv = w[c * DM + d];
#pragma unroll
        for (int r = 0; r < 8; ++r) acc[r] = fmaf(sf[r][c], wv, acc[r]);
    }
    float bv = b[d];
#pragma unroll
    for (int r = 0; r < 8; ++r)
        g_x[(size_t)(n0 + r) * DM + d] = acc[r] + bv;
    if (t < 8) {
        int n = n0 + t;
        float x0 = xyz[(size_t)n * 3 + 0];
        float x1 = xyz[(size_t)n * 3 + 1];
        float x2 = xyz[(size_t)n * 3 + 2];
        float sq = __fadd_rn(__fadd_rn(__fmul_rn(x0, x0), __fmul_rn(x1, x1)), __fmul_rn(x2, x2));
        g_xyzw[n] = make_float4(x0, x1, x2, 0.5f * sq);
    }
}

// ---------------- kernel 2: KNN — 2 threads/query, register top-K (R15 locked) ----------------
#define KNN_SMEM (16384 + 24576 + 24576)
__global__ void __launch_bounds__(256) k_knn() {
    extern __shared__ char sm[];
    float4* tile = reinterpret_cast<float4*>(sm);              // [1024]
    float*  skey = reinterpret_cast<float*>(sm + 16384);       // [128][48]
    int*    sidx = reinterpret_cast<int*>(sm + 16384 + 24576); // [128][48]

    int tid = threadIdx.x;
    int ql = tid & 127;
    int p = tid >> 7;
    int q = blockIdx.x * 128 + ql;
    int base = (q >> 13) << 13;

    float4 qv = g_xyzw[q];
    float qnx = -qv.x, qny = -qv.y, qnz = -qv.z;

    float kd[KNN];
    int   ki[KNN];
#pragma unroll
    for (int i = 0; i < KNN; ++i) { kd[i] = INFINITY; ki[i] = 0x7fffffff; }
    float wk = INFINITY;

    for (int t0 = 0; t0 < NPTS; t0 += 1024) {
        __syncthreads();
        for (int i = tid; i < 1024; i += 256)
            tile[i] = g_xyzw[base + t0 + i];
        __syncthreads();
        const float4* tp = tile + p * 512;
        int ib = t0 + p * 512;
        for (int i = 0; i < 512; ++i) {
            float4 c = tp[i];
            float key = __fmaf_rn(qnx, c.x, __fmaf_rn(qny, c.y, __fmaf_rn(qnz, c.z, c.w)));
            if (key < wk) {
                int bestki = -1, sel = 0;
#pragma unroll
                for (int k = 0; k < KNN; ++k) {
                    bool m = (kd[k] == wk) && (ki[k] > bestki);
                    if (m) { bestki = ki[k]; sel = k; }
                }
#pragma unroll
                for (int k = 0; k < KNN; ++k) {
                    if (k == sel) { kd[k] = key; ki[k] = ib + i; }
                }
                float m0 = kd[0];
#pragma unroll
                for (int k = 1; k < KNN; ++k) m0 = fmaxf(m0, kd[k]);
                wk = m0;
            }
        }
    }

    float* myk = skey + ql * 48 + p * 24;
    int*   myi = sidx + ql * 48 + p * 24;
#pragma unroll 1
    for (int k = 0; k < KNN; ++k) {
        float bk = kd[0]; int bi = ki[0]; int bs = 0;
#pragma unroll
        for (int j = 1; j < KNN; ++j) {
            bool lt = (kd[j] < bk) || (kd[j] == bk && ki[j] < bi);
            if (lt) { bk = kd[j]; bi = ki[j]; bs = j; }
        }
        myk[k] = bk; myi[k] = bi;
#pragma unroll
        for (int j = 0; j < KNN; ++j) {
            if (j == bs) { kd[j] = INFINITY; ki[j] = 0x7fffffff; }
        }
    }
    __syncthreads();

    if (p == 0) {
        const float* k0 = skey + ql * 48;
        const int*   i0 = sidx + ql * 48;
        const float* k1 = k0 + 24;
        const int*   i1 = i0 + 24;
        int a = 0, b = 0;
#pragma unroll
        for (int k = 0; k < KNN; ++k) {
            float ka = k0[a], kb = k1[b];
            int ia = i0[a], ic = i1[b];
            bool takeA = (ka < kb) || (ka == kb && ia < ic);
            g_idx[(size_t)q * KNN + k] = takeA ? ia : ic;
            if (takeA) ++a; else ++b;
        }
    }
}

// ---------------- kernel 3: pe + h1, 2 nodes per 256-thread block ----------------
__global__ void __launch_bounds__(256) k_pe(const float* __restrict__ d1w,
                                            const float* __restrict__ d1b) {
    int n0 = blockIdx.x * 2;
    int t = threadIdx.x;
    int nl = t >> 7;
    int d = t & 127;
    int nn = n0 + nl;

    __shared__ float w1[PE_D * DM];
    __shared__ float pe_t[2][PE_D * KNN];
    __shared__ float gk[2][KNN][3];

    for (int e = t; e < PE_D * DM; e += 256) w1[e] = d1w[e];
    if (t < 2 * KNN * 3) {
        int nodeL = t / (KNN * 3);
        int rem = t % (KNN * 3);
        int k = rem / 3, c = rem % 3;
        int node = n0 + nodeL;
        int bb = (node >> 13) << 13;
        int id = g_idx[(size_t)node * KNN + k];
        float4 q = g_xyzw[node];
        float4 cc = g_xyzw[bb + id];
        float qc = (c == 0) ? q.x : (c == 1) ? q.y : q.z;
        float kc = (c == 0) ? cc.x : (c == 1) ? cc.y : cc.z;
        gk[nodeL][k][c] = qc - kc;
    }
    __syncthreads();

    const float LOGC = -1.3287712379549449f;
    for (int e = t; e < 2 * KNN * PE_D; e += 256) {
        int nodeL = e / (KNN * PE_D);
        int rem = e % (KNN * PE_D);
        int k = rem / PE_D, j = rem % PE_D;
        int c = j / 20, r = j % 20, m = r % 10;
        float om = exp2f((float)m * LOGC);
        float ph = gk[nodeL][k][c] * om;
        pe_t[nodeL][j * KNN + k] = (r < 10) ? __sinf(ph) : __cosf(ph);
    }
    __syncthreads();

    unsigned long long acc2[12];
#pragma unroll
    for (int m = 0; m < 12; ++m) acc2[m] = 0ull;
    for (int j = 0; j < PE_D; ++j) {
        float wv = w1[j * DM + d];
        unsigned long long w2 = pk2(wv, wv);
        const unsigned long long* pr =
            reinterpret_cast<const unsigned long long*>(&pe_t[nl][j * KNN]);
#pragma unroll
        for (int m = 0; m < 12; ++m) fma2(acc2[m], pr[m], w2);
    }
    float bv = d1b[d];
#pragma unroll
    for (int m = 0; m < 12; ++m) {
        float a0, a1;
        upk2(acc2[m], a0, a1);
        g_bufA[((size_t)nn * KNN + 2 * m) * DM + d] = fmaxf(a0 + bv, 0.0f);
        g_bufA[((size_t)nn * KNN + 2 * m + 1) * DM + d] = fmaxf(a1 + bv, 0.0f);
    }
}

// ---------------- triple-buffered cp.async f32x2 GEMM (trailing sync removed) ----------------
// MODE 0 (BM=128): pos_enc->bufB, attn_in->bufA
// MODE 1 (BM=128): relu -> C (in-place bufA)
// MODE 2 (BM=96) : fused bias+softmax+weighted-sum -> attn to C, res0
#define AS_STRIDE 36
#define WS_BUF (32 * 128)          // floats per W buffer

template <int MODE, int BM>
__global__ void __launch_bounds__(256, 2)
k_gemm2(const float* __restrict__ A, const float* __restrict__ W,
        const float* __restrict__ bias, float* __restrict__ C) {
    constexpr int AS_BUF = BM * AS_STRIDE;
    constexpr int RPT = BM / 16;            // rows per thread
    extern __shared__ float smf[];
    float* Asm = smf;                   // [3][BM][36]
    float* Wsm = smf + 3 * AS_BUF;      // [3][32][128]
    uint32_t sA = smem_u32(Asm);
    uint32_t sW = smem_u32(Wsm);

    int r0 = blockIdx.x * BM;
    int tid = threadIdx.x;
    int tx = tid & 15, ty = tid >> 4;

    unsigned long long acc2[RPT][4];
#pragma unroll
    for (int i = 0; i < RPT; ++i)
#pragma unroll
        for (int j = 0; j < 4; ++j) acc2[i][j] = 0ull;

    // prologue: tile 0 -> buffers 0
    {
#pragma unroll
        for (int u = 0; u < BM / 32; ++u) {
            int e = tid + u * 256;
            int row = e >> 3, c = e & 7;
            uint32_t sa = sA + (uint32_t)(row * AS_STRIDE + c * 4) * 4;
            const float* ga = A + (size_t)(r0 + row) * 128 + c * 4;
            asm volatile("cp.async.cg.shared.global [%0], [%1], 16;" :: "r"(sa), "l"(ga));
        }
#pragma unroll
        for (int u = 0; u < 4; ++u) {
            int e = tid + u * 256;
            int kr = e >> 5, c = e & 31;
            uint32_t sw = sW + (uint32_t)(kr * 128 + c * 4) * 4;
            const float* gw = W + (size_t)kr * 128 + c * 4;
            asm volatile("cp.async.cg.shared.global [%0], [%1], 16;" :: "r"(sw), "l"(gw));
        }
        asm volatile("cp.async.commit_group;");
    }

#pragma unroll 1
    for (int kt = 0; kt < 128; kt += 32) {
        int m = kt >> 5;
        int buf = m % 3;
        if (kt < 96) {
            int nb = (m + 1) % 3;
#pragma unroll
            for (int u = 0; u < BM / 32; ++u) {
                int e = tid + u * 256;
                int row = e >> 3, c = e & 7;
                uint32_t sa = sA + (uint32_t)(nb * AS_BUF + row * AS_STRIDE + c * 4) * 4;
                const float* ga = A + (size_t)(r0 + row) * 128 + (kt + 32) + c * 4;
                asm volatile("cp.async.cg.shared.global [%0], [%1], 16;" :: "r"(sa), "l"(ga));
            }
#pragma unroll
            for (int u = 0; u < 4; ++u) {
                int e = tid + u * 256;
                int kr = e >> 5, c = e & 31;
                uint32_t sw = sW + (uint32_t)(nb * WS_BUF + kr * 128 + c * 4) * 4;
                const float* gw = W + (size_t)(kt + 32 + kr) * 128 + c * 4;
                asm volatile("cp.async.cg.shared.global [%0], [%1], 16;" :: "r"(sw), "l"(gw));
            }
            asm volatile("cp.async.commit_group;");
            asm volatile("cp.async.wait_group 1;");
        } else {
            asm volatile("cp.async.wait_group 0;");
        }
        __syncthreads();

        const float* Ab = Asm + buf * AS_BUF + (ty * RPT) * AS_STRIDE;
        const float* Wb = Wsm + buf * WS_BUF;
#pragma unroll
        for (int kk = 0; kk < 32; ++kk) {
            ulonglong2 wq0 = *reinterpret_cast<const ulonglong2*>(Wb + kk * 128 + tx * 8);
            ulonglong2 wq1 = *reinterpret_cast<const ulonglong2*>(Wb + kk * 128 + tx * 8 + 4);
            unsigned long long w2[4] = {wq0.x, wq0.y, wq1.x, wq1.y};
#pragma unroll
            for (int i = 0; i < RPT; ++i) {
                float av = Ab[i * AS_STRIDE + kk];
                unsigned long long a2 = pk2(av, av);
#pragma unroll
                for (int j = 0; j < 4; ++j) fma2(acc2[i][j], a2, w2[j]);
            }
        }
        // no trailing sync: next iteration's prefetch targets (m+2)%3, never the
        // buffer lagging warps (skew <= 1 iteration, enforced by leading barrier) read.
    }

    int col = tx * 8;

    if (MODE == 2) {
        // ---- fused bias + softmax + weighted sum (BM = 96 = 4 nodes) ----
        float* stage = smf;                         // [96][132], raw scores
        __syncthreads();                            // all compute reads of smem done
#pragma unroll
        for (int i = 0; i < RPT; ++i) {
            int row = ty * RPT + i;
            float o[8];
#pragma unroll
            for (int j = 0; j < 4; ++j) upk2(acc2[i][j], o[2 * j], o[2 * j + 1]);
#pragma unroll
            for (int j = 0; j < 4; ++j)
                *reinterpret_cast<float2*>(stage + row * 132 + col + 2 * j) =
                    make_float2(o[2 * j], o[2 * j + 1]);
        }
        __syncthreads();

        const float inv = 0.088388347648318447f;    // 1/sqrt(128)
#pragma unroll 1
        for (int jb = 0; jb < 2; ++jb) {
            int job = tid + jb * 256;               // 0..511
            int nl = job >> 7;                      // node-local 0..3
            int cc = job & 127;
            int node = blockIdx.x * 4 + nl;
            int base = (node >> 13) << 13;
            float bc = bias[cc];

            float a[KNN];
#pragma unroll
            for (int k = 0; k < KNN; ++k)
                a[k] = (stage[(nl * KNN + k) * 132 + cc] + bc) * inv;
            float m = a[0];
#pragma unroll
            for (int k = 1; k < KNN; ++k) m = fmaxf(m, a[k]);
            float s = 0.0f;
#pragma unroll
            for (int k = 0; k < KNN; ++k) { a[k] = expf(a[k] - m); s += a[k]; }
            float rs = 1.0f / s;

            float acc = 0.0f;
            size_t roff = (size_t)node * KNN * DM + cc;
#pragma unroll
            for (int k = 0; k < KNN; ++k) {
                float at = a[k] * rs;
                size_t po = roff + (size_t)k * DM;
                C[po] = at;
                int id = g_idx[(size_t)node * KNN + k];
                float vv = g_x[(size_t)(base + id) * DM + cc] + g_bufB[po];
                acc = fmaf(at, vv, acc);
            }
            g_res0[(size_t)node * DM + cc] = acc;
        }
        return;
    }

    // ---- modes 0/1 epilogue (registers + gmem only; no smem hazard) ----
    float4 b0 = *reinterpret_cast<const float4*>(bias + col);
    float4 b1 = *reinterpret_cast<const float4*>(bias + col + 4);
    float bc[8] = {b0.x, b0.y, b0.z, b0.w, b1.x, b1.y, b1.z, b1.w};

#pragma unroll
    for (int i = 0; i < RPT; ++i) {
        int R = r0 + ty * RPT + i;
        float o[8];
#pragma unroll
        for (int j = 0; j < 4; ++j) upk2(acc2[i][j], o[2 * j], o[2 * j + 1]);
#pragma unroll
        for (int j = 0; j < 8; ++j) o[j] += bc[j];
        size_t off = (size_t)R * 128 + col;
        if (MODE == 1) {
            *reinterpret_cast<float4*>(C + off) =
                make_float4(fmaxf(o[0], 0.f), fmaxf(o[1], 0.f), fmaxf(o[2], 0.f), fmaxf(o[3], 0.f));
            *reinterpret_cast<float4*>(C + off + 4) =
                make_float4(fmaxf(o[4], 0.f), fmaxf(o[5], 0.f), fmaxf(o[6], 0.f), fmaxf(o[7], 0.f));
        } else {
            int n = R / KNN;
            int kid = g_idx[R];
            int base = (n >> 13) << 13;
            const float* xn = g_x + (size_t)n * 128 + col;
            const float* xk = g_x + (size_t)(base + kid) * 128 + col;
            float4 n0 = *reinterpret_cast<const float4*>(xn);
            float4 n1 = *reinterpret_cast<const float4*>(xn + 4);
            float4 k0 = *reinterpret_cast<const float4*>(xk);
            float4 k1 = *reinterpret_cast<const float4*>(xk + 4);
            *reinterpret_cast<float4*>(g_bufB + off) = make_float4(o[0], o[1], o[2], o[3]);
            *reinterpret_cast<float4*>(g_bufB + off + 4) = make_float4(o[4], o[5], o[6], o[7]);
            float4 A0 = make_float4((n0.x - k0.x) + o[0], (n0.y - k0.y) + o[1],
                                    (n0.z - k0.z) + o[2], (n0.w - k0.w) + o[3]);
            float4 A1 = make_float4((n1.x - k1.x) + o[4], (n1.y - k1.y) + o[5],
                                    (n1.z - k1.z) + o[6], (n1.w - k1.w) + o[7]);
            *reinterpret_cast<float4*>(g_bufA + off) = A0;
            *reinterpret_cast<float4*>(g_bufA + off + 4) = A1;
        }
    }
}

// ---------------- final: out = res0@fc2 + b + x ----------------
__global__ void k_final(const float* __restrict__ w, const float* __restrict__ b,
                        float* __restrict__ out_res) {
    __shared__ float s[8][DM];
    int n0 = blockIdx.x * 8;
    int t = threadIdx.x;
    for (int e = t; e < 8 * DM; e += 128)
        s[e >> 7][e & 127] = g_res0[(size_t)(n0 + (e >> 7)) * DM + (e & 127)];
    __syncthreads();
    float acc[8];
#pragma unroll
    for (int r = 0; r < 8; ++r) acc[r] = 0.0f;
    for (int c = 0; c < DM; ++c) {
        float wv = w[c * DM + t];
#pragma unroll
        for (int r = 0; r < 8; ++r) acc[r] = fmaf(s[r][c], wv, acc[r]);
    }
    float bv = b[t];
#pragma unroll
    for (int r = 0; r < 8; ++r)
        out_res[(size_t)(n0 + r) * DM + t] = (acc[r] + bv) + g_x[(size_t)(n0 + r) * DM + t];
}

// ---------------- launch ----------------
extern "C" void kernel_launch(void* const* d_in, const int* in_sizes, int n_in,
                              void* d_out, int out_size) {
    const float* features = (const float*)d_in[0];
    const float* xyz      = (const float*)d_in[1];
    const float* fc1_w    = (const float*)d_in[2];
    const float* fc1_b    = (const float*)d_in[3];
    const float* fc2_w    = (const float*)d_in[4];
    const float* fc2_b    = (const float*)d_in[5];
    const float* d1_w     = (const float*)d_in[6];
    const float* d1_b     = (const float*)d_in[7];
    const float* d2_w     = (const float*)d_in[8];
    const float* d2_b     = (const float*)d_in[9];
    const float* g1_w     = (const float*)d_in[10];
    const float* g1_b     = (const float*)d_in[11];
    const float* g2_w     = (const float*)d_in[12];
    const float* g2_b     = (const float*)d_in[13];

    float* out      = (float*)d_out;
    float* out_res  = out;
    float* out_attn = out + (size_t)NB * DM;

    float *pA = nullptr;
    cudaGetSymbolAddress((void**)&pA, g_bufA);

    // smem: BM=128: (3*128*36 + 3*32*128)*4 = 104448 B (2 CTAs = 204 KB <= 228 KB)
    //       BM=96 : max((3*96*36 + 3*32*128)*4, 96*132*4) = max(90624, 50688) = 90624
    const int SM128 = (3 * 128 * AS_STRIDE + 3 * WS_BUF) * 4;
    const int SM96a = (3 * 96 * AS_STRIDE + 3 * WS_BUF) * 4;
    const int SM96b = 96 * 132 * 4;
    const int SM96 = SM96a > SM96b ? SM96a : SM96b;
    cudaFuncSetAttribute((const void*)k_knn, cudaFuncAttributeMaxDynamicSharedMemorySize, KNN_SMEM);
    cudaFuncSetAttribute((const void*)k_gemm2<0, 128>, cudaFuncAttributeMaxDynamicSharedMemorySize, SM128);
    cudaFuncSetAttribute((const void*)k_gemm2<1, 128>, cudaFuncAttributeMaxDynamicSharedMemorySize, SM128);
    cudaFuncSetAttribute((const void*)k_gemm2<2, 96>,  cudaFuncAttributeMaxDynamicSharedMemorySize, SM96);

    // 1. x = features@fc1 + b ; xyzw pack (w = 0.5*||p||^2)
    k_fc1<<<NB / 8, 128>>>(features, xyz, fc1_w, fc1_b);
    // 2. KNN (locked R15)
    k_knn<<<NB / 128, 256, KNN_SMEM>>>();
    // 3. h1 = relu(pe@d1 + b) -> bufA  (2 nodes/block)
    k_pe<<<NB / 2, 256>>>(d1_w, d1_b);
    // 4. pos_enc -> bufB ; attn_in -> bufA (fused epilogue)
    k_gemm2<0, 128><<<RROWS / 128, 256, SM128>>>(pA, d2_w, d2_b, nullptr);
    // 5. h2 = relu(attn_in@g1 + b) -> bufA (in-place per-CTA, safe)
    k_gemm2<1, 128><<<RROWS / 128, 256, SM128>>>(pA, g1_w, g1_b, pA);
    // 6. attn = softmax(h2@g2 + b) -> out_attn ; res0 (fused)
    k_gemm2<2, 96><<<RROWS / 96, 256, SM96>>>(pA, g2_w, g2_b, out_attn);
    // 7. res = res0@fc2 + b + x
    k_final<<<NB / 8, 128>>>(fc2_w, fc2_b, out_res);
}